// round 17
// baseline (speedup 1.0000x reference)
#include <cuda_runtime.h>
#include <math.h>

#define NN 3000
#define EE 48000
#define FF 32
#define GRID 200
#define TPB 480            // 15 warps, 1 row per warp, 15 rows per block (exact)
#define NWARP 15
#define EXCL 1200
#define KSELF 10800.0f
#define ROWCAP 64
#define NRMAX 15

// ---------------- static global state ----------------
__device__ unsigned int g_gen[(size_t)NN * NN];   // 36 MB dedup generations (never zeroed)
__device__ unsigned int g_run;                     // run epoch (bumped by finalizer)
__device__ int g_deg[NN];                          // re-zeroed each run by owners
__device__ int g_rcnt[NN];
__device__ unsigned short g_cols[NN * ROWCAP];
__device__ float g_A[NN * FF];
__device__ float g_B[NN * FF];
__device__ float g_C[NN * FF];
__device__ float g_Y1[NN * FF];
__device__ float g_X1[NN * FF];
__device__ unsigned long long g_keys[NN];
__device__ float g_part[GRID * FF];
__device__ unsigned int g_ctr;                     // ticket barrier counter (monotonic)

// ---------------- R5 ticket barrier (measured optimum) ----------------
__device__ __forceinline__ void gsync() {
    __syncthreads();
    if (threadIdx.x == 0) {
        unsigned int old;
        asm volatile("atom.release.gpu.add.u32 %0, [%1], 1;"
                     : "=r"(old) : "l"(&g_ctr) : "memory");
        unsigned int target = old - (old % GRID) + GRID;   // next multiple of GRID
        unsigned int v;
        do {
            asm volatile("ld.acquire.gpu.u32 %0, [%1];" : "=r"(v) : "l"(&g_ctr) : "memory");
        } while ((int)(v - target) < 0);
    }
    __syncthreads();
}

__device__ __forceinline__ unsigned int f2ord(float f) {
    unsigned int u = __float_as_uint(f);
    return (u & 0x80000000u) ? ~u : (u | 0x80000000u);
}

// ---------------- the one persistent kernel ----------------
__global__ void __launch_bounds__(TPB, 2)
cayley_all(const float* __restrict__ x, const int* __restrict__ ei,
           const float* __restrict__ ph, const float* __restrict__ palpha,
           const float* __restrict__ Wr0, const float* __restrict__ Wc0a,
           const float* __restrict__ Wc0b, const float* __restrict__ Wr1,
           const float* __restrict__ Wc1a, const float* __restrict__ Wc1b,
           const float* __restrict__ pw, const float* __restrict__ lw,
           const float* __restrict__ lb, float* __restrict__ out) {
    // s_raw: 6 weight matrices (24576B) during phases; keys (24000B) alias at rank; partials after
    __shared__ __align__(16) unsigned char s_raw[24576 + NWARP * FF * 4];
    __shared__ __align__(8) float2 s_ew[NRMAX * ROWCAP];   // (byte-offset bits, weight) per edge
    __shared__ int s_cnt[NRMAX];
    __shared__ float s_sinv[NRMAX];
    __shared__ int s_last;

    const int tid  = threadIdx.x;
    const int lane = tid & 31;
    const int wid  = tid >> 5;
    const int bid  = blockIdx.x;

    const int r0    = bid * NRMAX;            // exact 15 rows per block
    const int nrows = NRMAX;

    const unsigned int gen = g_run + 1u;      // unique per run (runs serialize)

    const int* rowp = ei;
    const int* colp = ei + EE;
    const float hh = __ldg(ph);
    const float aa = __ldg(palpha);

    // pool_w norm
    float pwv = __ldg(pw + lane);
    float nv = pwv * pwv;
#pragma unroll
    for (int o = 16; o > 0; o >>= 1) nv += __shfl_xor_sync(0xffffffffu, nv, o);
    const float pnorm = sqrtf(nv);

    // ---- stage all 6 weight matrices (transposed) once; ordered before use by B1 ----
    {
        float* sW = (float*)s_raw;
        for (int t = tid; t < FF * FF; t += TPB) {
            int f = t >> 5, k = t & 31;
            sW[k * FF + f]        = __ldg(Wr0 + t);
            sW[1024 + k * FF + f] = __ldg(Wc0a + t);
            sW[2048 + k * FF + f] = __ldg(Wc0b + t);
            sW[3072 + k * FF + f] = __ldg(Wr1 + t);
            sW[4096 + k * FF + f] = __ldg(Wc1a + t);
            sW[5120 + k * FF + f] = __ldg(Wc1b + t);
        }
    }

    // ---- S1: distributed edge build (200*480 = 96000 >= EE) ----
    {
        int e = bid * TPB + tid;
        if (e < EE) {
            int r = __ldg(rowp + e), c = __ldg(colp + e);
            atomicAdd(&g_deg[r], 1);                              // degree with multiplicity
            unsigned int old = atomicMax(&g_gen[(size_t)r * NN + c], gen);
            if (old < gen) {                                      // first occurrence this run
                int pos = atomicAdd(&g_rcnt[r], 1);
                if (pos < ROWCAP) g_cols[r * ROWCAP + pos] = (unsigned short)c;
            }
        }
    }
    gsync();   // B1

    // ---- CSR -> smem + weights ----
    {
        if (tid < nrows) {
            int r = r0 + tid;
            int c2 = g_rcnt[r];
            s_cnt[tid] = c2 > ROWCAP ? ROWCAP : c2;
            s_sinv[tid] = 1.0f / ((float)g_deg[r] - aa);
        }
        __syncthreads();
        for (int idx = tid; idx < NRMAX * ROWCAP; idx += TPB) {
            int lr = idx >> 6, j = idx & 63;
            if (j < s_cnt[lr]) {
                int c = (int)g_cols[(r0 + lr) * ROWCAP + j];
                float w = 1.0f / (((float)g_deg[c] - aa) * hh);   // invD[col]
                s_ew[idx] = make_float2(__int_as_float(c * (FF * 4)), w);
            }
        }
        __syncthreads();
    }

#define ROW_BJAC(IN, RES) do { \
        int r = r0 + wid; \
        float diag = __ldcg((IN) + r * FF + lane); \
        int cnt = s_cnt[wid]; \
        const float2* ep = s_ew + wid * ROWCAP; \
        float acc = 0.f; \
        _Pragma("unroll 8") \
        for (int j = 0; j < cnt; ++j) { \
            float2 e = ep[j]; \
            acc += __ldcg((const float*)((const char*)(IN) + __float_as_int(e.x)) + lane); \
        } \
        RES = diag - s_sinv[wid] * acc; \
    } while (0)

    // jac with b_j carried in register (own-row value from the chain's bjac)
#define ROW_JACR(YK, BJREG, RES) do { \
        int cnt = s_cnt[wid]; \
        const float2* ep = s_ew + wid * ROWCAP; \
        float acc = 0.f; \
        _Pragma("unroll 8") \
        for (int j = 0; j < cnt; ++j) { \
            float2 e = ep[j]; \
            acc += e.y * __ldcg((const float*)((const char*)(YK) + __float_as_int(e.x)) + lane); \
        } \
        RES = acc + (BJREG); \
    } while (0)

#define PHASE_BJAC(IN, OUT, BJREG) do { \
        { ROW_BJAC(IN, BJREG); \
          OUT[(r0 + wid) * FF + lane] = BJREG; } \
        gsync(); } while (0)

#define PHASE_JAC(YK, BJREG, OUT) do { \
        { float rres; ROW_JACR(YK, BJREG, rres); \
          OUT[(r0 + wid) * FF + lane] = rres; } \
        gsync(); } while (0)

    float myscore = 0.f, myxout = 0.f;
    float bjv = 0.f;
    const float* sW = (const float*)s_raw;

    // ---- layer 0 order 0 ----
    PHASE_BJAC(x, g_A, bjv);       // B2
    PHASE_JAC(g_A, bjv, g_B);      // B3
    PHASE_JAC(g_B, bjv, g_C);      // B4
    PHASE_JAC(g_C, bjv, g_B);      // B5
    PHASE_JAC(g_B, bjv, g_C);      // B6
    PHASE_JAC(g_C, bjv, g_Y1);     // B7

    // ---- layer 0 order 1 ----
    PHASE_BJAC(g_Y1, g_A, bjv);    // B8
    PHASE_JAC(g_A, bjv, g_B);      // B9
    PHASE_JAC(g_B, bjv, g_C);      // B10
    PHASE_JAC(g_C, bjv, g_B);      // B11
    PHASE_JAC(g_B, bjv, g_C);      // B12
    // fused last jac + outgemm -> X1
    {
        {
            int r = r0 + wid;
            float y2; ROW_JACR(g_C, bjv, y2);
            float y1 = __ldcg(g_Y1 + r * FF + lane);
            float xo = __ldg(x + r * FF + lane);
            float acc = 0.f;
#pragma unroll
            for (int k = 0; k < FF; ++k) {
                float xv  = __shfl_sync(0xffffffffu, xo, k);
                float y1v = __shfl_sync(0xffffffffu, y1, k);
                float y2v = __shfl_sync(0xffffffffu, y2, k);
                acc += xv * sW[k * FF + lane]
                     + 2.f * y1v * sW[1024 + k * FF + lane]
                     + 2.f * y2v * sW[2048 + k * FF + lane];
            }
            g_X1[r * FF + lane] = fmaxf(acc, 0.f);
        }
        gsync();   // B13
    }

    // ---- layer 1 order 0 ----
    PHASE_BJAC(g_X1, g_A, bjv);    // B14
    PHASE_JAC(g_A, bjv, g_B);      // B15
    PHASE_JAC(g_B, bjv, g_C);      // B16
    PHASE_JAC(g_C, bjv, g_B);      // B17
    PHASE_JAC(g_B, bjv, g_C);      // B18
    PHASE_JAC(g_C, bjv, g_Y1);     // B19

    // ---- layer 1 order 1 ----
    PHASE_BJAC(g_Y1, g_A, bjv);    // B20
    PHASE_JAC(g_A, bjv, g_B);      // B21
    PHASE_JAC(g_B, bjv, g_C);      // B22
    PHASE_JAC(g_C, bjv, g_B);      // B23
    PHASE_JAC(g_B, bjv, g_C);      // B24
    // fused last jac + outgemm + score/keys (X2 stays in registers)
    {
        {
            int r = r0 + wid;
            float y2; ROW_JACR(g_C, bjv, y2);
            float y1 = __ldcg(g_Y1 + r * FF + lane);
            float xo = __ldcg(g_X1 + r * FF + lane);
            float acc = 0.f;
#pragma unroll
            for (int k = 0; k < FF; ++k) {
                float xv  = __shfl_sync(0xffffffffu, xo, k);
                float y1v = __shfl_sync(0xffffffffu, y1, k);
                float y2v = __shfl_sync(0xffffffffu, y2, k);
                acc += xv * sW[3072 + k * FF + lane]
                     + 2.f * y1v * sW[4096 + k * FF + lane]
                     + 2.f * y2v * sW[5120 + k * FF + lane];
            }
            myxout = fmaxf(acc, 0.f);
            float v = myxout * pwv;
#pragma unroll
            for (int o = 16; o > 0; o >>= 1) v += __shfl_xor_sync(0xffffffffu, v, o);
            myscore = tanhf(v / pnorm);
            if (lane == 0)
                g_keys[r] = ((unsigned long long)f2ord(myscore) << 32)
                          | (unsigned long long)(0xFFFFFFFFu - (unsigned int)r);
        }
        gsync();   // B25
    }

    // ---- rank + weighted partial sums + counter re-zero + ARRIVE (no poll) ----
    {
        unsigned long long* sk = (unsigned long long*)s_raw;   // weights dead now
        float* spart = (float*)(s_raw + 24576);
        for (int i = tid; i < NN; i += TPB)
            sk[i] = __ldcg((const unsigned long long*)(g_keys + i));
        if (tid < nrows) { g_deg[r0 + tid] = 0; g_rcnt[r0 + tid] = 0; }
        __syncthreads();
        float contrib = 0.f;
        {
            int r = r0 + wid;
            unsigned long long ki = ((unsigned long long)f2ord(myscore) << 32)
                                  | (unsigned long long)(0xFFFFFFFFu - (unsigned int)r);
            int c2 = 0;
            for (int j = lane; j < NN; j += 32) c2 += (sk[j] < ki) ? 1 : 0;
#pragma unroll
            for (int o = 16; o > 0; o >>= 1) c2 += __shfl_xor_sync(0xffffffffu, c2, o);
            float coef = (c2 < EXCL && myscore < 0.f) ? 0.f : myscore;
            contrib = coef * myxout;
        }
        spart[wid * FF + lane] = contrib;
        __syncthreads();
        if (wid == 0) {
            float t = 0.f;
#pragma unroll
            for (int q = 0; q < NWARP; ++q) t += spart[q * FF + lane];
            g_part[bid * FF + lane] = t;
        }
        // final arrival: release my g_part, detect last arriver; NO polling
        __syncthreads();
        if (tid == 0) {
            unsigned int old;
            asm volatile("atom.acq_rel.gpu.add.u32 %0, [%1], 1;"
                         : "=r"(old) : "l"(&g_ctr) : "memory");
            s_last = (old % GRID == GRID - 1u) ? 1 : 0;
        }
        __syncthreads();
    }

    // ---- LAST ARRIVER ONLY: final reduce + linear + run-epoch bump ----
    if (s_last && wid == 0) {
        float t = 0.f;
        for (int b = 0; b < GRID; ++b)
            t += __ldcg(g_part + b * FF + lane);
        float* sg = (float*)(s_raw + 24576);
        sg[lane] = t * (1.0f / KSELF);
        __syncwarp();
        if (lane < 8) {
            float o = __ldg(lb + lane);
#pragma unroll
            for (int f = 0; f < FF; ++f) o += sg[f] * __ldg(lw + lane * FF + f);
            out[lane] = o;
        }
        if (lane == 0) g_run = gen;   // epoch for next run (runs serialize at kernel boundary)
    }
}

// ---------------- host side ----------------
extern "C" void kernel_launch(void* const* d_in, const int* in_sizes, int n_in,
                              void* d_out, int out_size) {
    const float* x     = (const float*)d_in[0];
    const int*   ei    = (const int*)d_in[1];
    const float* h     = (const float*)d_in[2];
    const float* alpha = (const float*)d_in[3];
    const float* Wr0   = (const float*)d_in[4];
    const float* Wc0a  = (const float*)d_in[5];
    const float* Wc0b  = (const float*)d_in[6];
    const float* Wr1   = (const float*)d_in[7];
    const float* Wc1a  = (const float*)d_in[8];
    const float* Wc1b  = (const float*)d_in[9];
    const float* pw    = (const float*)d_in[10];
    const float* lw    = (const float*)d_in[11];
    const float* lb    = (const float*)d_in[12];

    cayley_all<<<GRID, TPB>>>(x, ei, h, alpha, Wr0, Wc0a, Wc0b,
                              Wr1, Wc1a, Wc1b, pw, lw, lb, (float*)d_out);
}